// round 8
// baseline (speedup 1.0000x reference)
#include <cuda_runtime.h>
#include <cuda_bf16.h>
#include <mma.h>
#include <cstdint>

using namespace nvcuda;

#define T_SEQ 512
#define B_SZ  256
#define IN_D  64
#define H_D   128
#define G4    512
#define TB    (T_SEQ * B_SZ)

__device__ float g_bufA[TB * H_D];
__device__ float g_bufB[TB * H_D];
__device__ float g_pre [TB * G4];

// ---------------- helpers ----------------
__device__ __forceinline__ uint32_t smem_u32(const void* p) {
    uint32_t a;
    asm("{ .reg .u64 t; cvta.to.shared.u64 t, %1; cvt.u32.u64 %0, t; }"
        : "=r"(a) : "l"(p));
    return a;
}
__device__ __forceinline__ void fma2(unsigned long long &acc,
                                     unsigned long long a, unsigned long long b) {
    asm("fma.rn.f32x2 %0, %1, %2, %3;" : "=l"(acc) : "l"(a), "l"(b), "l"(acc));
}
__device__ __forceinline__ unsigned long long pack2(float lo, float hi) {
    unsigned long long r;
    asm("mov.b64 %0, {%1, %2};" : "=l"(r) : "f"(lo), "f"(hi));
    return r;
}
__device__ __forceinline__ float sum2(unsigned long long v) {
    float lo, hi;
    asm("mov.b64 {%0, %1}, %2;" : "=f"(lo), "=f"(hi) : "l"(v));
    return lo + hi;
}
__device__ __forceinline__ float fsig(float x) {
    return __fdividef(1.0f, 1.0f + __expf(-x));
}
__device__ __forceinline__ float ftanh(float x) {
    return __fdividef(2.0f, 1.0f + __expf(-2.0f * x)) - 1.0f;
}
__device__ __forceinline__ void split2(float a, float b,
                                       __nv_bfloat162 &h, __nv_bfloat162 &l) {
    const __nv_bfloat16 ha = __float2bfloat16_rn(a);
    const __nv_bfloat16 hb = __float2bfloat16_rn(b);
    h.x = ha; h.y = hb;
    l.x = __float2bfloat16_rn(a - __bfloat162float(ha));
    l.y = __float2bfloat16_rn(b - __bfloat162float(hb));
}

// ============================================================================
// pregemm: pre[TB,512] = X[TB,K] @ W[512,K]^T + bih + bhh
// wmma bf16 hi/lo split (3 mma per k-tile). CTA tile 64(M) x 128(N), full K
// in smem. B stored TRANSPOSED [k][n] so both fragments load row_major
// (plain ldmatrix). +8-element padding -> conflict-free LDSM.
// 102.5KB smem -> 2 CTAs/SM. grid = (TB/64)*4, n-inner for A L2 reuse.
// ============================================================================
template<int K>
__global__ void __launch_bounds__(256, 2)
pregemm(const float* __restrict__ X, const float* __restrict__ W,
        const float* __restrict__ bih, const float* __restrict__ bhh,
        float* __restrict__ pre)
{
    constexpr int AS = K + 8;      // A row stride (bf16 elements)
    constexpr int BS = 128 + 8;    // B row stride (n elements)
    extern __shared__ __align__(256) char smp[];
    float* bias = (float*)smp;                           // 128 f32
    __nv_bfloat16* Ah = (__nv_bfloat16*)(smp + 512);     // [64][AS]
    __nv_bfloat16* Al = Ah + 64 * AS;
    __nv_bfloat16* Bh = Al + 64 * AS;                    // [K][BS]
    __nv_bfloat16* Bl = Bh + K * BS;
    float* Dsm = (float*)(smp + 512);                    // [64][128] (reuse)

    const int tid = threadIdx.x;
    const int wid = tid >> 5;
    const int m0 = (int)(blockIdx.x >> 2) * 64;
    const int n0 = (int)(blockIdx.x & 3) * 128;

    if (tid < 128) bias[tid] = bih[n0 + tid] + bhh[n0 + tid];

    // A tile: [64][K] f32 -> bf16 hi/lo, row-major padded
    for (int i = tid; i < 64 * K / 4; i += 256) {
        const int r = i / (K / 4), c4 = (i % (K / 4)) * 4;
        float4 v = *(const float4*)(X + (size_t)(m0 + r) * K + c4);
        __nv_bfloat162 h0, l0, h1, l1;
        split2(v.x, v.y, h0, l0);
        split2(v.z, v.w, h1, l1);
        *(__nv_bfloat162*)(Ah + r * AS + c4)     = h0;
        *(__nv_bfloat162*)(Ah + r * AS + c4 + 2) = h1;
        *(__nv_bfloat162*)(Al + r * AS + c4)     = l0;
        *(__nv_bfloat162*)(Al + r * AS + c4 + 2) = l1;
    }
    // B tile: W[n][k] -> Bs[k][n] (transposed), padded
    for (int i = tid; i < 128 * K / 4; i += 256) {
        const int n = i / (K / 4), c4 = (i % (K / 4)) * 4;
        float4 v = *(const float4*)(W + (size_t)(n0 + n) * K + c4);
        __nv_bfloat162 h0, l0, h1, l1;
        split2(v.x, v.y, h0, l0);
        split2(v.z, v.w, h1, l1);
        Bh[(c4 + 0) * BS + n] = h0.x;  Bl[(c4 + 0) * BS + n] = l0.x;
        Bh[(c4 + 1) * BS + n] = h0.y;  Bl[(c4 + 1) * BS + n] = l0.y;
        Bh[(c4 + 2) * BS + n] = h1.x;  Bl[(c4 + 2) * BS + n] = l1.x;
        Bh[(c4 + 3) * BS + n] = h1.y;  Bl[(c4 + 3) * BS + n] = l1.y;
    }
    __syncthreads();

    const int wm = wid >> 1;    // 0..3 -> m rows [wm*16, +16)
    const int wn = wid & 1;     // 0..1 -> n cols [wn*64, +64)

    wmma::fragment<wmma::accumulator, 16, 16, 16, float> acc[4];
#pragma unroll
    for (int ni = 0; ni < 4; ni++) wmma::fill_fragment(acc[ni], 0.0f);

#pragma unroll
    for (int ks = 0; ks < K / 16; ks++) {
        wmma::fragment<wmma::matrix_a, 16, 16, 16, __nv_bfloat16,
                       wmma::row_major> ah, al;
        wmma::load_matrix_sync(ah, Ah + (wm * 16) * AS + ks * 16, AS);
        wmma::load_matrix_sync(al, Al + (wm * 16) * AS + ks * 16, AS);
#pragma unroll
        for (int ni = 0; ni < 4; ni++) {
            wmma::fragment<wmma::matrix_b, 16, 16, 16, __nv_bfloat16,
                           wmma::row_major> bhf, blf;
            wmma::load_matrix_sync(bhf,
                Bh + ks * 16 * BS + wn * 64 + ni * 16, BS);
            wmma::load_matrix_sync(blf,
                Bl + ks * 16 * BS + wn * 64 + ni * 16, BS);
            wmma::mma_sync(acc[ni], ah, bhf, acc[ni]);   // hi*hi
            wmma::mma_sync(acc[ni], ah, blf, acc[ni]);   // hi*lo
            wmma::mma_sync(acc[ni], al, bhf, acc[ni]);   // lo*hi
        }
    }
    __syncthreads();   // smem A/B reads done; reuse as D

#pragma unroll
    for (int ni = 0; ni < 4; ni++)
        wmma::store_matrix_sync(
            Dsm + (wm * 16) * 128 + wn * 64 + ni * 16,
            acc[ni], 128, wmma::mem_row_major);
    __syncthreads();

    for (int i = tid; i < 64 * 32; i += 256) {
        const int r = i >> 5, c4 = (i & 31) * 4;
        float4 v = *(const float4*)(Dsm + r * 128 + c4);
        v.x += bias[c4];     v.y += bias[c4 + 1];
        v.z += bias[c4 + 2]; v.w += bias[c4 + 3];
        *(float4*)(pre + (size_t)(m0 + r) * G4 + n0 + c4) = v;
    }
}

// ============================================================================
// lstm_rec: gates = pre[t] + h(t-1) @ Whh^T ; persistent, cluster of 4.
// Cluster barrier replaced by a 4-count mbarrier handshake:
//   end of step t: __syncthreads -> tid0 arrives (release.cluster) on all 4
//   ranks' mbarriers;  step t waits parity t&1 (acquire.cluster, ~60-90 cyc
//   wakeup vs ~490 for barrier.cluster, and no L1 flush).
// ============================================================================
__global__ void __launch_bounds__(512, 1) __cluster_dims__(4, 1, 1)
lstm_rec(const float* __restrict__ pre,   // [T,B,512], biases included
         float* __restrict__ out,         // [T,B,128]
         const float* __restrict__ Whh)   // [512,128]
{
    __shared__ float gbuf[8][8][128];
    __shared__ __align__(16) float hs[2][8][128];
    __shared__ __align__(8) unsigned long long hmb;

    const int tid = threadIdx.x, lane = tid & 31, w = tid >> 5;
    const int rg = w & 1, slq = w >> 1;
    uint32_t rank;
    asm("mov.u32 %0, %%cluster_ctarank;" : "=r"(rank));
    const int sl = (slq + 2 * (int)rank) & 7;
    const int k0 = sl * 16;
    const bool own = (slq < 2);
    const int b0 = (blockIdx.x >> 2) * 8;
    const uint32_t mb = smem_u32(&hmb);

    const int r0 = rg * 64 + lane, r1 = r0 + 32;
    const int gr0 = (r0 >> 5) * H_D + (int)rank * 32 + (r0 & 31);
    const int gr1 = (r1 >> 5) * H_D + (int)rank * 32 + (r1 & 31);

    unsigned long long W0[8], W1[8];
#pragma unroll
    for (int i = 0; i < 8; i++) {
        W0[i] = pack2(Whh[gr0 * H_D + k0 + 2 * i], Whh[gr0 * H_D + k0 + 2 * i + 1]);
        W1[i] = pack2(Whh[gr1 * H_D + k0 + 2 * i], Whh[gr1 * H_D + k0 + 2 * i + 1]);
    }

    const int ob = tid >> 5, oj = tid & 31;
    const int jglob = (int)rank * 32 + oj;
    float c_state = 0.0f;
    const float* pre_p = pre + ((size_t)b0 + ob) * G4 + jglob;
    float* out_p = out + ((size_t)b0 + ob) * H_D + jglob;

    if (tid == 0)
        asm volatile("mbarrier.init.shared.b64 [%0], 4;" :: "r"(mb) : "memory");
    for (int i = tid; i < 8 * H_D; i += 512) hs[0][i >> 7][i & 127] = 0.0f;
    __syncthreads();
    // all CTAs' mbarriers initialized before any remote arrive
    asm volatile("barrier.cluster.arrive.aligned;" ::: "memory");
    asm volatile("barrier.cluster.wait.aligned;"   ::: "memory");
    if (tid == 0) {
#pragma unroll
        for (int pr = 0; pr < 4; pr++)
            asm volatile("{ .reg .b32 ra;\n\t"
                "mapa.shared::cluster.u32 ra, %0, %1;\n\t"
                "mbarrier.arrive.release.cluster.shared::cluster.b64 _, [ra]; }"
                :: "r"(mb), "r"(pr) : "memory");
    }

    for (int t = 0; t < T_SEQ; t++) {
        const int cur = t & 1, nxt = cur ^ 1;
        const uint32_t ph = (uint32_t)(t & 1);

        float p0, p1, p2, p3;
        if (tid < 256) {
            p0 = pre_p[0];   p1 = pre_p[128];
            p2 = pre_p[256]; p3 = pre_p[384];
            pre_p += (size_t)B_SZ * G4;
        }

        if (own) {   // local h columns: ordered by the trailing __syncthreads
            const float* h0 = &hs[cur][0][k0];
            float* g0 = &gbuf[slq][0][0];
#pragma unroll
            for (int p = 0; p < 2; p++) {
                unsigned long long a0[4] = {0,0,0,0}, a1[4] = {0,0,0,0};
#pragma unroll
                for (int kk = 0; kk < 4; kk++)
#pragma unroll
                    for (int b = 0; b < 4; b++) {
                        ulonglong2 v = *(const ulonglong2*)(h0 + (p * 4 + b) * 128 + 4 * kk);
                        fma2(a0[b], v.x, W0[2 * kk]); fma2(a0[b], v.y, W0[2 * kk + 1]);
                        fma2(a1[b], v.x, W1[2 * kk]); fma2(a1[b], v.y, W1[2 * kk + 1]);
                    }
#pragma unroll
                for (int b = 0; b < 4; b++) {
                    g0[(p * 4 + b) * 128 + r0] = sum2(a0[b]);
                    g0[(p * 4 + b) * 128 + r1] = sum2(a1[b]);
                }
            }
        }

        // wait for h(t-1) publishes from all 4 ranks (parity t&1)
        {
            uint32_t done;
            asm volatile("{\n\t.reg .pred p;\n\t"
                "mbarrier.try_wait.parity.acquire.cluster.shared::cta.b64 p, [%1], %2;\n\t"
                "selp.b32 %0, 1, 0, p;\n\t}"
                : "=r"(done) : "r"(mb), "r"(ph) : "memory");
            if (!done) {
                asm volatile("{\n\t.reg .pred P1;\n\tWL%=:\n\t"
                    "mbarrier.try_wait.parity.acquire.cluster.shared::cta.b64 P1, [%0], %1, 0x989680;\n\t"
                    "@P1 bra.uni WD%=;\n\tbra.uni WL%=;\n\tWD%=:\n\t}"
                    :: "r"(mb), "r"(ph) : "memory");
            }
        }

        if (!own) {  // peer h columns
            const float* h0 = &hs[cur][0][k0];
            float* g0 = &gbuf[slq][0][0];
#pragma unroll
            for (int p = 0; p < 2; p++) {
                unsigned long long a0[4] = {0,0,0,0}, a1[4] = {0,0,0,0};
#pragma unroll
                for (int kk = 0; kk < 4; kk++)
#pragma unroll
                    for (int b = 0; b < 4; b++) {
                        ulonglong2 v = *(const ulonglong2*)(h0 + (p * 4 + b) * 128 + 4 * kk);
                        fma2(a0[b], v.x, W0[2 * kk]); fma2(a0[b], v.y, W0[2 * kk + 1]);
                        fma2(a1[b], v.x, W1[2 * kk]); fma2(a1[b], v.y, W1[2 * kk + 1]);
                    }
#pragma unroll
                for (int b = 0; b < 4; b++) {
                    g0[(p * 4 + b) * 128 + r0] = sum2(a0[b]);
                    g0[(p * 4 + b) * 128 + r1] = sum2(a1[b]);
                }
            }
        }

        __syncthreads();

        if (tid < 256) {
            float gv0 = p0, gv1 = p1, gv2 = p2, gv3 = p3;
#pragma unroll
            for (int q = 0; q < 8; q++) {
                gv0 += gbuf[q][ob][oj];
                gv1 += gbuf[q][ob][32 + oj];
                gv2 += gbuf[q][ob][64 + oj];
                gv3 += gbuf[q][ob][96 + oj];
            }
            const float ig = fsig(gv0), fg = fsig(gv1);
            const float gg = ftanh(gv2), og = fsig(gv3);
            c_state = fg * c_state + ig * gg;
            const float h = og * ftanh(c_state);

            if (t + 1 < T_SEQ) {
                float* hp = &hs[nxt][ob][jglob];
                *hp = h;
                const uint32_t la = (uint32_t)__cvta_generic_to_shared(hp);
#pragma unroll
                for (int pr = 0; pr < 4; pr++)
                    if (pr != (int)rank)
                        asm volatile("{ .reg .b32 ra;\n\t"
                            "mapa.shared::cluster.u32 ra, %0, %1;\n\t"
                            "st.shared::cluster.f32 [ra], %2; }"
                            :: "r"(la), "r"(pr), "f"(h) : "memory");
            }
            *out_p = h;
            out_p += (size_t)B_SZ * H_D;
        }

        __syncthreads();   // all h stores done; gbuf consumed

        if (tid == 0 && t + 1 < T_SEQ) {
#pragma unroll
            for (int pr = 0; pr < 4; pr++)
                asm volatile("{ .reg .b32 ra;\n\t"
                    "mapa.shared::cluster.u32 ra, %0, %1;\n\t"
                    "mbarrier.arrive.release.cluster.shared::cluster.b64 _, [ra]; }"
                    :: "r"(mb), "r"(pr) : "memory");
        }
    }
}

// ============================================================================
extern "C" void kernel_launch(void* const* d_in, const int* in_sizes, int n_in,
                              void* d_out, int out_size) {
    const float* x     = (const float*)d_in[0];
    const float* Wih0  = (const float*)d_in[1];
    const float* Wrest = (const float*)d_in[2];
    const float* Whh   = (const float*)d_in[3];
    const float* bih   = (const float*)d_in[4];
    const float* bhh   = (const float*)d_in[5];
    float* out = (float*)d_out;

    float *bufA, *bufB, *preb;
    cudaGetSymbolAddress((void**)&bufA, g_bufA);
    cudaGetSymbolAddress((void**)&bufB, g_bufB);
    cudaGetSymbolAddress((void**)&preb, g_pre);

    // smem: 512 + A(64*(K+8)*4) + B(K*136*4) bytes
    const int SP64  = 512 + 64 * 72  * 4 + 64  * 136 * 4;   //  53760
    const int SP128 = 512 + 64 * 136 * 4 + 128 * 136 * 4;   // 104960
    cudaFuncSetAttribute(pregemm<64>,
        cudaFuncAttributeMaxDynamicSharedMemorySize, SP64);
    cudaFuncSetAttribute(pregemm<128>,
        cudaFuncAttributeMaxDynamicSharedMemorySize, SP128);

    float* lay_out[5] = {bufA, bufB, bufA, bufB, out};

    pregemm<64><<<8192, 256, SP64>>>(x, Wih0, bih, bhh, preb);
    lstm_rec<<<128, 512>>>(preb, lay_out[0], Whh);
    for (int l = 1; l < 5; l++) {
        pregemm<128><<<8192, 256, SP128>>>(
            lay_out[l - 1], Wrest + (size_t)(l - 1) * G4 * H_D,
            bih + (size_t)l * G4, bhh + (size_t)l * G4, preb);
        lstm_rec<<<128, 512>>>(preb, lay_out[l], Whh + (size_t)l * G4 * H_D);
    }
}

// round 9
// speedup vs baseline: 1.2724x; 1.2724x over previous
#include <cuda_runtime.h>
#include <cuda_bf16.h>
#include <mma.h>
#include <cstdint>

using namespace nvcuda;

#define T_SEQ 512
#define B_SZ  256
#define IN_D  64
#define H_D   128
#define G4    512
#define TB    (T_SEQ * B_SZ)

__device__ float g_bufA[TB * H_D];
__device__ float g_bufB[TB * H_D];
__device__ float g_pre [TB * G4];

// ---------------- helpers ----------------
__device__ __forceinline__ void fma2(unsigned long long &acc,
                                     unsigned long long a, unsigned long long b) {
    asm("fma.rn.f32x2 %0, %1, %2, %3;" : "=l"(acc) : "l"(a), "l"(b), "l"(acc));
}
__device__ __forceinline__ unsigned long long pack2(float lo, float hi) {
    unsigned long long r;
    asm("mov.b64 %0, {%1, %2};" : "=l"(r) : "f"(lo), "f"(hi));
    return r;
}
__device__ __forceinline__ float sum2(unsigned long long v) {
    float lo, hi;
    asm("mov.b64 {%0, %1}, %2;" : "=f"(lo), "=f"(hi) : "l"(v));
    return lo + hi;
}
__device__ __forceinline__ float fsig(float x) {
    return __fdividef(1.0f, 1.0f + __expf(-x));
}
__device__ __forceinline__ float ftanh(float x) {
    return __fdividef(2.0f, 1.0f + __expf(-2.0f * x)) - 1.0f;
}
__device__ __forceinline__ void split2(float a, float b,
                                       __nv_bfloat162 &h, __nv_bfloat162 &l) {
    const __nv_bfloat16 ha = __float2bfloat16_rn(a);
    const __nv_bfloat16 hb = __float2bfloat16_rn(b);
    h.x = ha; h.y = hb;
    l.x = __float2bfloat16_rn(a - __bfloat162float(ha));
    l.y = __float2bfloat16_rn(b - __bfloat162float(hb));
}

// ============================================================================
// pregemm (R8-measured-good): pre[TB,512] = X[TB,K] @ W[512,K]^T + bih + bhh
// wmma bf16 hi/lo split. CTA tile 64(M) x 128(N), full K in smem.
// B transposed [k][n] (both fragments row_major), +8 padding -> no conflicts.
// 2 CTAs/SM. grid = (TB/64)*4, n-inner for A L2 reuse.
// ============================================================================
template<int K>
__global__ void __launch_bounds__(256, 2)
pregemm(const float* __restrict__ X, const float* __restrict__ W,
        const float* __restrict__ bih, const float* __restrict__ bhh,
        float* __restrict__ pre)
{
    constexpr int AS = K + 8;
    constexpr int BS = 128 + 8;
    extern __shared__ __align__(256) char smp[];
    float* bias = (float*)smp;
    __nv_bfloat16* Ah = (__nv_bfloat16*)(smp + 512);
    __nv_bfloat16* Al = Ah + 64 * AS;
    __nv_bfloat16* Bh = Al + 64 * AS;
    __nv_bfloat16* Bl = Bh + K * BS;
    float* Dsm = (float*)(smp + 512);

    const int tid = threadIdx.x;
    const int wid = tid >> 5;
    const int m0 = (int)(blockIdx.x >> 2) * 64;
    const int n0 = (int)(blockIdx.x & 3) * 128;

    if (tid < 128) bias[tid] = bih[n0 + tid] + bhh[n0 + tid];

    for (int i = tid; i < 64 * K / 4; i += 256) {
        const int r = i / (K / 4), c4 = (i % (K / 4)) * 4;
        float4 v = *(const float4*)(X + (size_t)(m0 + r) * K + c4);
        __nv_bfloat162 h0, l0, h1, l1;
        split2(v.x, v.y, h0, l0);
        split2(v.z, v.w, h1, l1);
        *(__nv_bfloat162*)(Ah + r * AS + c4)     = h0;
        *(__nv_bfloat162*)(Ah + r * AS + c4 + 2) = h1;
        *(__nv_bfloat162*)(Al + r * AS + c4)     = l0;
        *(__nv_bfloat162*)(Al + r * AS + c4 + 2) = l1;
    }
    for (int i = tid; i < 128 * K / 4; i += 256) {
        const int n = i / (K / 4), c4 = (i % (K / 4)) * 4;
        float4 v = *(const float4*)(W + (size_t)(n0 + n) * K + c4);
        __nv_bfloat162 h0, l0, h1, l1;
        split2(v.x, v.y, h0, l0);
        split2(v.z, v.w, h1, l1);
        Bh[(c4 + 0) * BS + n] = h0.x;  Bl[(c4 + 0) * BS + n] = l0.x;
        Bh[(c4 + 1) * BS + n] = h0.y;  Bl[(c4 + 1) * BS + n] = l0.y;
        Bh[(c4 + 2) * BS + n] = h1.x;  Bl[(c4 + 2) * BS + n] = l1.x;
        Bh[(c4 + 3) * BS + n] = h1.y;  Bl[(c4 + 3) * BS + n] = l1.y;
    }
    __syncthreads();

    const int wm = wid >> 1;
    const int wn = wid & 1;

    wmma::fragment<wmma::accumulator, 16, 16, 16, float> acc[4];
#pragma unroll
    for (int ni = 0; ni < 4; ni++) wmma::fill_fragment(acc[ni], 0.0f);

#pragma unroll
    for (int ks = 0; ks < K / 16; ks++) {
        wmma::fragment<wmma::matrix_a, 16, 16, 16, __nv_bfloat16,
                       wmma::row_major> ah, al;
        wmma::load_matrix_sync(ah, Ah + (wm * 16) * AS + ks * 16, AS);
        wmma::load_matrix_sync(al, Al + (wm * 16) * AS + ks * 16, AS);
#pragma unroll
        for (int ni = 0; ni < 4; ni++) {
            wmma::fragment<wmma::matrix_b, 16, 16, 16, __nv_bfloat16,
                           wmma::row_major> bhf, blf;
            wmma::load_matrix_sync(bhf,
                Bh + ks * 16 * BS + wn * 64 + ni * 16, BS);
            wmma::load_matrix_sync(blf,
                Bl + ks * 16 * BS + wn * 64 + ni * 16, BS);
            wmma::mma_sync(acc[ni], ah, bhf, acc[ni]);
            wmma::mma_sync(acc[ni], ah, blf, acc[ni]);
            wmma::mma_sync(acc[ni], al, bhf, acc[ni]);
        }
    }
    __syncthreads();

#pragma unroll
    for (int ni = 0; ni < 4; ni++)
        wmma::store_matrix_sync(
            Dsm + (wm * 16) * 128 + wn * 64 + ni * 16,
            acc[ni], 128, wmma::mem_row_major);
    __syncthreads();

    for (int i = tid; i < 64 * 32; i += 256) {
        const int r = i >> 5, c4 = (i & 31) * 4;
        float4 v = *(const float4*)(Dsm + r * 128 + c4);
        v.x += bias[c4];     v.y += bias[c4 + 1];
        v.z += bias[c4 + 2]; v.w += bias[c4 + 3];
        *(float4*)(pre + (size_t)(m0 + r) * G4 + n0 + c4) = v;
    }
}

// ============================================================================
// lstm_rec (R7-measured-good, barrier.cluster version):
// gates = pre[t] + h(t-1) @ Whh^T ; persistent, cluster of 4.
// 16 warps: slice sl = (w>>1 + 2*rank)&7 (16 k each), 2 gate rows/thread.
// Own-slice warps (local h cols) run BEFORE cluster wait to hide the barrier.
// ============================================================================
__global__ void __launch_bounds__(512, 1) __cluster_dims__(4, 1, 1)
lstm_rec(const float* __restrict__ pre,   // [T,B,512], biases included
         float* __restrict__ out,         // [T,B,128]
         const float* __restrict__ Whh)   // [512,128]
{
    __shared__ float gbuf[8][8][128];
    __shared__ __align__(16) float hs[2][8][128];

    const int tid = threadIdx.x, lane = tid & 31, w = tid >> 5;
    const int rg = w & 1, slq = w >> 1;
    uint32_t rank;
    asm("mov.u32 %0, %%cluster_ctarank;" : "=r"(rank));
    const int sl = (slq + 2 * (int)rank) & 7;
    const int k0 = sl * 16;
    const bool own = (slq < 2);
    const int b0 = (blockIdx.x >> 2) * 8;

    const int r0 = rg * 64 + lane, r1 = r0 + 32;
    const int gr0 = (r0 >> 5) * H_D + (int)rank * 32 + (r0 & 31);
    const int gr1 = (r1 >> 5) * H_D + (int)rank * 32 + (r1 & 31);

    unsigned long long W0[8], W1[8];
#pragma unroll
    for (int i = 0; i < 8; i++) {
        W0[i] = pack2(Whh[gr0 * H_D + k0 + 2 * i], Whh[gr0 * H_D + k0 + 2 * i + 1]);
        W1[i] = pack2(Whh[gr1 * H_D + k0 + 2 * i], Whh[gr1 * H_D + k0 + 2 * i + 1]);
    }

    const int ob = tid >> 5, oj = tid & 31;
    const int jglob = (int)rank * 32 + oj;
    float c_state = 0.0f;
    const float* pre_p = pre + ((size_t)b0 + ob) * G4 + jglob;
    float* out_p = out + ((size_t)b0 + ob) * H_D + jglob;

    for (int i = tid; i < 8 * H_D; i += 512) hs[0][i >> 7][i & 127] = 0.0f;
    __syncthreads();
    asm volatile("barrier.cluster.arrive.aligned;" ::: "memory");

    for (int t = 0; t < T_SEQ; t++) {
        const int cur = t & 1, nxt = cur ^ 1;

        float p0, p1, p2, p3;
        if (tid < 256) {
            p0 = pre_p[0];   p1 = pre_p[128];
            p2 = pre_p[256]; p3 = pre_p[384];
            pre_p += (size_t)B_SZ * G4;
        }

        if (own) {   // local h columns: ordered by __syncthreads, not barrier
            const float* h0 = &hs[cur][0][k0];
            float* g0 = &gbuf[slq][0][0];
#pragma unroll
            for (int p = 0; p < 2; p++) {
                unsigned long long a0[4] = {0,0,0,0}, a1[4] = {0,0,0,0};
#pragma unroll
                for (int kk = 0; kk < 4; kk++)
#pragma unroll
                    for (int b = 0; b < 4; b++) {
                        ulonglong2 v = *(const ulonglong2*)(h0 + (p * 4 + b) * 128 + 4 * kk);
                        fma2(a0[b], v.x, W0[2 * kk]); fma2(a0[b], v.y, W0[2 * kk + 1]);
                        fma2(a1[b], v.x, W1[2 * kk]); fma2(a1[b], v.y, W1[2 * kk + 1]);
                    }
#pragma unroll
                for (int b = 0; b < 4; b++) {
                    g0[(p * 4 + b) * 128 + r0] = sum2(a0[b]);
                    g0[(p * 4 + b) * 128 + r1] = sum2(a1[b]);
                }
            }
        }

        asm volatile("barrier.cluster.wait.aligned;" ::: "memory");

        if (!own) {  // peer h columns: need the cluster barrier
            const float* h0 = &hs[cur][0][k0];
            float* g0 = &gbuf[slq][0][0];
#pragma unroll
            for (int p = 0; p < 2; p++) {
                unsigned long long a0[4] = {0,0,0,0}, a1[4] = {0,0,0,0};
#pragma unroll
                for (int kk = 0; kk < 4; kk++)
#pragma unroll
                    for (int b = 0; b < 4; b++) {
                        ulonglong2 v = *(const ulonglong2*)(h0 + (p * 4 + b) * 128 + 4 * kk);
                        fma2(a0[b], v.x, W0[2 * kk]); fma2(a0[b], v.y, W0[2 * kk + 1]);
                        fma2(a1[b], v.x, W1[2 * kk]); fma2(a1[b], v.y, W1[2 * kk + 1]);
                    }
#pragma unroll
                for (int b = 0; b < 4; b++) {
                    g0[(p * 4 + b) * 128 + r0] = sum2(a0[b]);
                    g0[(p * 4 + b) * 128 + r1] = sum2(a1[b]);
                }
            }
        }

        __syncthreads();

        if (tid < 256) {
            float gv0 = p0, gv1 = p1, gv2 = p2, gv3 = p3;
#pragma unroll
            for (int q = 0; q < 8; q++) {
                gv0 += gbuf[q][ob][oj];
                gv1 += gbuf[q][ob][32 + oj];
                gv2 += gbuf[q][ob][64 + oj];
                gv3 += gbuf[q][ob][96 + oj];
            }
            const float ig = fsig(gv0), fg = fsig(gv1);
            const float gg = ftanh(gv2), og = fsig(gv3);
            c_state = fg * c_state + ig * gg;
            const float h = og * ftanh(c_state);

            if (t + 1 < T_SEQ) {
                float* hp = &hs[nxt][ob][jglob];
                *hp = h;
                const uint32_t la = (uint32_t)__cvta_generic_to_shared(hp);
#pragma unroll
                for (int pr = 0; pr < 4; pr++)
                    if (pr != (int)rank)
                        asm volatile("{ .reg .b32 ra;\n\t"
                            "mapa.shared::cluster.u32 ra, %0, %1;\n\t"
                            "st.shared::cluster.f32 [ra], %2; }"
                            :: "r"(la), "r"(pr), "f"(h) : "memory");
            }
            *out_p = h;
            out_p += (size_t)B_SZ * H_D;
        }

        if (t + 1 < T_SEQ)
            asm volatile("barrier.cluster.arrive.aligned;" ::: "memory");
        __syncthreads();
    }
}

// ============================================================================
extern "C" void kernel_launch(void* const* d_in, const int* in_sizes, int n_in,
                              void* d_out, int out_size) {
    const float* x     = (const float*)d_in[0];
    const float* Wih0  = (const float*)d_in[1];
    const float* Wrest = (const float*)d_in[2];
    const float* Whh   = (const float*)d_in[3];
    const float* bih   = (const float*)d_in[4];
    const float* bhh   = (const float*)d_in[5];
    float* out = (float*)d_out;

    float *bufA, *bufB, *preb;
    cudaGetSymbolAddress((void**)&bufA, g_bufA);
    cudaGetSymbolAddress((void**)&bufB, g_bufB);
    cudaGetSymbolAddress((void**)&preb, g_pre);

    const int SP64  = 512 + 64 * 72  * 4 + 64  * 136 * 4;   //  53760
    const int SP128 = 512 + 64 * 136 * 4 + 128 * 136 * 4;   // 104960
    cudaFuncSetAttribute(pregemm<64>,
        cudaFuncAttributeMaxDynamicSharedMemorySize, SP64);
    cudaFuncSetAttribute(pregemm<128>,
        cudaFuncAttributeMaxDynamicSharedMemorySize, SP128);

    float* lay_out[5] = {bufA, bufB, bufA, bufB, out};

    pregemm<64><<<8192, 256, SP64>>>(x, Wih0, bih, bhh, preb);
    lstm_rec<<<128, 512>>>(preb, lay_out[0], Whh);
    for (int l = 1; l < 5; l++) {
        pregemm<128><<<8192, 256, SP128>>>(
            lay_out[l - 1], Wrest + (size_t)(l - 1) * G4 * H_D,
            bih + (size_t)l * G4, bhh + (size_t)l * G4, preb);
        lstm_rec<<<128, 512>>>(preb, lay_out[l], Whh + (size_t)l * G4 * H_D);
    }
}

// round 10
// speedup vs baseline: 1.6466x; 1.2941x over previous
#include <cuda_runtime.h>
#include <cuda_bf16.h>
#include <mma.h>
#include <cstdint>

using namespace nvcuda;

#define T_SEQ 512
#define B_SZ  256
#define IN_D  64
#define H_D   128
#define G4    512
#define TB    (T_SEQ * B_SZ)

__device__ float g_bufA[TB * H_D];                  // dummy f32 sink (layers 0-3)
__device__ float g_pre [TB * G4];                   // gate pre-activations
__device__ __nv_bfloat16 g_ah[TB * H_D];            // activations hi (bf16)
__device__ __nv_bfloat16 g_al[TB * H_D];            // activations lo (bf16)
__device__ __nv_bfloat16 g_wh[H_D * G4];            // W^T hi  [K][512]
__device__ __nv_bfloat16 g_wl[H_D * G4];            // W^T lo  [K][512]

// ---------------- helpers ----------------
__device__ __forceinline__ void fma2(unsigned long long &acc,
                                     unsigned long long a, unsigned long long b) {
    asm("fma.rn.f32x2 %0, %1, %2, %3;" : "=l"(acc) : "l"(a), "l"(b), "l"(acc));
}
__device__ __forceinline__ unsigned long long pack2(float lo, float hi) {
    unsigned long long r;
    asm("mov.b64 %0, {%1, %2};" : "=l"(r) : "f"(lo), "f"(hi));
    return r;
}
__device__ __forceinline__ float sum2(unsigned long long v) {
    float lo, hi;
    asm("mov.b64 {%0, %1}, %2;" : "=f"(lo), "=f"(hi) : "l"(v));
    return lo + hi;
}
__device__ __forceinline__ float fsig(float x) {
    return __fdividef(1.0f, 1.0f + __expf(-x));
}
__device__ __forceinline__ float ftanh(float x) {
    return __fdividef(2.0f, 1.0f + __expf(-2.0f * x)) - 1.0f;
}
__device__ __forceinline__ void split2(float a, float b,
                                       __nv_bfloat162 &h, __nv_bfloat162 &l) {
    const __nv_bfloat16 ha = __float2bfloat16_rn(a);
    const __nv_bfloat16 hb = __float2bfloat16_rn(b);
    h.x = ha; h.y = hb;
    l.x = __float2bfloat16_rn(a - __bfloat162float(ha));
    l.y = __float2bfloat16_rn(b - __bfloat162float(hb));
}

// ============================================================================
// xconvert: f32 -> bf16 hi/lo (layer-0 input only)
// ============================================================================
__global__ void xconvert(const float* __restrict__ x,
                         __nv_bfloat16* __restrict__ xh,
                         __nv_bfloat16* __restrict__ xl, int n4) {
    const int i = blockIdx.x * blockDim.x + threadIdx.x;
    if (i >= n4) return;
    const float4 v = ((const float4*)x)[i];
    __nv_bfloat162 h0, l0, h1, l1;
    split2(v.x, v.y, h0, l0);
    split2(v.z, v.w, h1, l1);
    ((__nv_bfloat162*)xh)[2 * i]     = h0;
    ((__nv_bfloat162*)xh)[2 * i + 1] = h1;
    ((__nv_bfloat162*)xl)[2 * i]     = l0;
    ((__nv_bfloat162*)xl)[2 * i + 1] = l1;
}

// ============================================================================
// wconvert: W[512][K] f32 -> W^T hi/lo bf16 [K][512] (coalesced writes)
// ============================================================================
__global__ void wconvert(const float* __restrict__ W,
                         __nv_bfloat16* __restrict__ wh,
                         __nv_bfloat16* __restrict__ wl, int K) {
    const int e = blockIdx.x * blockDim.x + threadIdx.x;
    if (e >= K * G4) return;
    const int k = e >> 9, n = e & 511;
    const float v = W[(size_t)n * K + k];
    const __nv_bfloat16 h = __float2bfloat16_rn(v);
    wh[e] = h;
    wl[e] = __float2bfloat16_rn(v - __bfloat162float(h));
}

// ============================================================================
// pregemm: pre[TB,512] = A[TB,K] @ W[512,K]^T + bih + bhh
// Operands arrive as pre-split bf16 (A row-major [TB][K], W^T [K][512]).
// Pure copy -> wmma (3 mma hi/lo split) -> store. CTA 64(M) x 128(N).
// Padded smem (conflict-free ldmatrix). 2 CTAs/SM. grid n-inner for A reuse.
// ============================================================================
template<int K>
__global__ void __launch_bounds__(256, 2)
pregemm(const __nv_bfloat16* __restrict__ Ahg,   // [TB][K]
        const __nv_bfloat16* __restrict__ Alg,
        const __nv_bfloat16* __restrict__ Bhg,   // [K][512]
        const __nv_bfloat16* __restrict__ Blg,
        const float* __restrict__ bih, const float* __restrict__ bhh,
        float* __restrict__ pre)
{
    constexpr int AS = K + 8;
    constexpr int BS = 128 + 8;
    extern __shared__ __align__(256) char smp[];
    float* bias = (float*)smp;
    __nv_bfloat16* Ah = (__nv_bfloat16*)(smp + 512);   // [64][AS]
    __nv_bfloat16* Al = Ah + 64 * AS;
    __nv_bfloat16* Bh = Al + 64 * AS;                  // [K][BS]
    __nv_bfloat16* Bl = Bh + K * BS;
    float* Dsm = (float*)(smp + 512);                  // [64][128] reuse

    const int tid = threadIdx.x;
    const int wid = tid >> 5;
    const int m0 = (int)(blockIdx.x >> 2) * 64;
    const int n0 = (int)(blockIdx.x & 3) * 128;

    if (tid < 128) bias[tid] = bih[n0 + tid] + bhh[n0 + tid];

    // A tiles: straight uint4 copies (8 bf16 per op), padded rows
    for (int i = tid; i < 64 * K / 8; i += 256) {
        const int r = i / (K / 8), c8 = (i % (K / 8)) * 8;
        *(uint4*)(Ah + r * AS + c8) =
            *(const uint4*)(Ahg + (size_t)(m0 + r) * K + c8);
        *(uint4*)(Al + r * AS + c8) =
            *(const uint4*)(Alg + (size_t)(m0 + r) * K + c8);
    }
    // B tiles: rows k, 128 cols starting at n0
    for (int i = tid; i < K * 16; i += 256) {
        const int k = i >> 4, c8 = (i & 15) * 8;
        *(uint4*)(Bh + k * BS + c8) =
            *(const uint4*)(Bhg + (size_t)k * G4 + n0 + c8);
        *(uint4*)(Bl + k * BS + c8) =
            *(const uint4*)(Blg + (size_t)k * G4 + n0 + c8);
    }
    __syncthreads();

    const int wm = wid >> 1;
    const int wn = wid & 1;

    wmma::fragment<wmma::accumulator, 16, 16, 16, float> acc[4];
#pragma unroll
    for (int ni = 0; ni < 4; ni++) wmma::fill_fragment(acc[ni], 0.0f);

#pragma unroll
    for (int ks = 0; ks < K / 16; ks++) {
        wmma::fragment<wmma::matrix_a, 16, 16, 16, __nv_bfloat16,
                       wmma::row_major> ah, al;
        wmma::load_matrix_sync(ah, Ah + (wm * 16) * AS + ks * 16, AS);
        wmma::load_matrix_sync(al, Al + (wm * 16) * AS + ks * 16, AS);
#pragma unroll
        for (int ni = 0; ni < 4; ni++) {
            wmma::fragment<wmma::matrix_b, 16, 16, 16, __nv_bfloat16,
                           wmma::row_major> bhf, blf;
            wmma::load_matrix_sync(bhf,
                Bh + ks * 16 * BS + wn * 64 + ni * 16, BS);
            wmma::load_matrix_sync(blf,
                Bl + ks * 16 * BS + wn * 64 + ni * 16, BS);
            wmma::mma_sync(acc[ni], ah, bhf, acc[ni]);   // hi*hi
            wmma::mma_sync(acc[ni], ah, blf, acc[ni]);   // hi*lo
            wmma::mma_sync(acc[ni], al, bhf, acc[ni]);   // lo*hi
        }
    }
    __syncthreads();

#pragma unroll
    for (int ni = 0; ni < 4; ni++)
        wmma::store_matrix_sync(
            Dsm + (wm * 16) * 128 + wn * 64 + ni * 16,
            acc[ni], 128, wmma::mem_row_major);
    __syncthreads();

    for (int i = tid; i < 64 * 32; i += 256) {
        const int r = i >> 5, c4 = (i & 31) * 4;
        float4 v = *(const float4*)(Dsm + r * 128 + c4);
        v.x += bias[c4];     v.y += bias[c4 + 1];
        v.z += bias[c4 + 2]; v.w += bias[c4 + 3];
        *(float4*)(pre + (size_t)(m0 + r) * G4 + n0 + c4) = v;
    }
}

// ============================================================================
// lstm_rec (measured-good 886us config): gates = pre[t] + h(t-1) @ Whh^T
// Persistent, cluster of 4. Epilogue additionally emits h as bf16 hi/lo
// (feeds the next layer's pregemm — no conversion kernel on the big tensors).
// ============================================================================
__global__ void __launch_bounds__(512, 1) __cluster_dims__(4, 1, 1)
lstm_rec(const float* __restrict__ pre,   // [T,B,512], biases included
         float* __restrict__ out,         // [T,B,128] f32
         const float* __restrict__ Whh,   // [512,128]
         __nv_bfloat16* __restrict__ gh,  // [T,B,128] h hi
         __nv_bfloat16* __restrict__ gl)  // [T,B,128] h lo
{
    __shared__ float gbuf[8][8][128];
    __shared__ __align__(16) float hs[2][8][128];

    const int tid = threadIdx.x, lane = tid & 31, w = tid >> 5;
    const int rg = w & 1, slq = w >> 1;
    uint32_t rank;
    asm("mov.u32 %0, %%cluster_ctarank;" : "=r"(rank));
    const int sl = (slq + 2 * (int)rank) & 7;
    const int k0 = sl * 16;
    const bool own = (slq < 2);
    const int b0 = (blockIdx.x >> 2) * 8;

    const int r0 = rg * 64 + lane, r1 = r0 + 32;
    const int gr0 = (r0 >> 5) * H_D + (int)rank * 32 + (r0 & 31);
    const int gr1 = (r1 >> 5) * H_D + (int)rank * 32 + (r1 & 31);

    unsigned long long W0[8], W1[8];
#pragma unroll
    for (int i = 0; i < 8; i++) {
        W0[i] = pack2(Whh[gr0 * H_D + k0 + 2 * i], Whh[gr0 * H_D + k0 + 2 * i + 1]);
        W1[i] = pack2(Whh[gr1 * H_D + k0 + 2 * i], Whh[gr1 * H_D + k0 + 2 * i + 1]);
    }

    const int ob = tid >> 5, oj = tid & 31;
    const int jglob = (int)rank * 32 + oj;
    float c_state = 0.0f;
    const float* pre_p = pre + ((size_t)b0 + ob) * G4 + jglob;
    float* out_p = out + ((size_t)b0 + ob) * H_D + jglob;
    __nv_bfloat16* gh_p = gh + ((size_t)b0 + ob) * H_D + jglob;
    __nv_bfloat16* gl_p = gl + ((size_t)b0 + ob) * H_D + jglob;

    for (int i = tid; i < 8 * H_D; i += 512) hs[0][i >> 7][i & 127] = 0.0f;
    __syncthreads();
    asm volatile("barrier.cluster.arrive.aligned;" ::: "memory");

    for (int t = 0; t < T_SEQ; t++) {
        const int cur = t & 1, nxt = cur ^ 1;

        float p0, p1, p2, p3;
        if (tid < 256) {
            p0 = pre_p[0];   p1 = pre_p[128];
            p2 = pre_p[256]; p3 = pre_p[384];
            pre_p += (size_t)B_SZ * G4;
        }

        if (own) {   // local h columns: ordered by __syncthreads, not barrier
            const float* h0 = &hs[cur][0][k0];
            float* g0 = &gbuf[slq][0][0];
#pragma unroll
            for (int p = 0; p < 2; p++) {
                unsigned long long a0[4] = {0,0,0,0}, a1[4] = {0,0,0,0};
#pragma unroll
                for (int kk = 0; kk < 4; kk++)
#pragma unroll
                    for (int b = 0; b < 4; b++) {
                        ulonglong2 v = *(const ulonglong2*)(h0 + (p * 4 + b) * 128 + 4 * kk);
                        fma2(a0[b], v.x, W0[2 * kk]); fma2(a0[b], v.y, W0[2 * kk + 1]);
                        fma2(a1[b], v.x, W1[2 * kk]); fma2(a1[b], v.y, W1[2 * kk + 1]);
                    }
#pragma unroll
                for (int b = 0; b < 4; b++) {
                    g0[(p * 4 + b) * 128 + r0] = sum2(a0[b]);
                    g0[(p * 4 + b) * 128 + r1] = sum2(a1[b]);
                }
            }
        }

        asm volatile("barrier.cluster.wait.aligned;" ::: "memory");

        if (!own) {  // peer h columns: need the cluster barrier
            const float* h0 = &hs[cur][0][k0];
            float* g0 = &gbuf[slq][0][0];
#pragma unroll
            for (int p = 0; p < 2; p++) {
                unsigned long long a0[4] = {0,0,0,0}, a1[4] = {0,0,0,0};
#pragma unroll
                for (int kk = 0; kk < 4; kk++)
#pragma unroll
                    for (int b = 0; b < 4; b++) {
                        ulonglong2 v = *(const ulonglong2*)(h0 + (p * 4 + b) * 128 + 4 * kk);
                        fma2(a0[b], v.x, W0[2 * kk]); fma2(a0[b], v.y, W0[2 * kk + 1]);
                        fma2(a1[b], v.x, W1[2 * kk]); fma2(a1[b], v.y, W1[2 * kk + 1]);
                    }
#pragma unroll
                for (int b = 0; b < 4; b++) {
                    g0[(p * 4 + b) * 128 + r0] = sum2(a0[b]);
                    g0[(p * 4 + b) * 128 + r1] = sum2(a1[b]);
                }
            }
        }

        __syncthreads();

        if (tid < 256) {
            float gv0 = p0, gv1 = p1, gv2 = p2, gv3 = p3;
#pragma unroll
            for (int q = 0; q < 8; q++) {
                gv0 += gbuf[q][ob][oj];
                gv1 += gbuf[q][ob][32 + oj];
                gv2 += gbuf[q][ob][64 + oj];
                gv3 += gbuf[q][ob][96 + oj];
            }
            const float ig = fsig(gv0), fg = fsig(gv1);
            const float gg = ftanh(gv2), og = fsig(gv3);
            c_state = fg * c_state + ig * gg;
            const float h = og * ftanh(c_state);

            if (t + 1 < T_SEQ) {
                float* hp = &hs[nxt][ob][jglob];
                *hp = h;
                const uint32_t la = (uint32_t)__cvta_generic_to_shared(hp);
#pragma unroll
                for (int pr = 0; pr < 4; pr++)
                    if (pr != (int)rank)
                        asm volatile("{ .reg .b32 ra;\n\t"
                            "mapa.shared::cluster.u32 ra, %0, %1;\n\t"
                            "st.shared::cluster.f32 [ra], %2; }"
                            :: "r"(la), "r"(pr), "f"(h) : "memory");
            }
            *out_p = h;
            out_p += (size_t)B_SZ * H_D;
            // bf16 hi/lo for the next layer's GEMM
            const __nv_bfloat16 hh = __float2bfloat16_rn(h);
            *gh_p = hh;
            *gl_p = __float2bfloat16_rn(h - __bfloat162float(hh));
            gh_p += (size_t)B_SZ * H_D;
            gl_p += (size_t)B_SZ * H_D;
        }

        if (t + 1 < T_SEQ)
            asm volatile("barrier.cluster.arrive.aligned;" ::: "memory");
        __syncthreads();
    }
}

// ============================================================================
extern "C" void kernel_launch(void* const* d_in, const int* in_sizes, int n_in,
                              void* d_out, int out_size) {
    const float* x     = (const float*)d_in[0];
    const float* Wih0  = (const float*)d_in[1];
    const float* Wrest = (const float*)d_in[2];
    const float* Whh   = (const float*)d_in[3];
    const float* bih   = (const float*)d_in[4];
    const float* bhh   = (const float*)d_in[5];
    float* out = (float*)d_out;

    float *bufA, *preb;
    __nv_bfloat16 *ah, *al, *wh, *wl;
    cudaGetSymbolAddress((void**)&bufA, g_bufA);
    cudaGetSymbolAddress((void**)&preb, g_pre);
    cudaGetSymbolAddress((void**)&ah, g_ah);
    cudaGetSymbolAddress((void**)&al, g_al);
    cudaGetSymbolAddress((void**)&wh, g_wh);
    cudaGetSymbolAddress((void**)&wl, g_wl);

    const int SP64  = 512 + 64 * 72  * 2 * 2 + 64  * 136 * 2 * 2;  //  53760
    const int SP128 = 512 + 64 * 136 * 2 * 2 + 128 * 136 * 2 * 2;  // 104960
    cudaFuncSetAttribute(pregemm<64>,
        cudaFuncAttributeMaxDynamicSharedMemorySize, SP64);
    cudaFuncSetAttribute(pregemm<128>,
        cudaFuncAttributeMaxDynamicSharedMemorySize, SP128);

    // layer 0
    xconvert<<<TB * IN_D / 4 / 256, 256>>>(x, ah, al, TB * IN_D / 4);
    wconvert<<<64 * G4 / 256, 256>>>(Wih0, wh, wl, 64);
    pregemm<64><<<8192, 256, SP64>>>(ah, al, wh, wl, bih, bhh, preb);
    lstm_rec<<<128, 512>>>(preb, bufA, Whh, ah, al);

    // layers 1..4
    for (int l = 1; l < 5; l++) {
        wconvert<<<128 * G4 / 256, 256>>>(
            Wrest + (size_t)(l - 1) * G4 * H_D, wh, wl, 128);
        pregemm<128><<<8192, 256, SP128>>>(
            ah, al, wh, wl, bih + (size_t)l * G4, bhh + (size_t)l * G4, preb);
        lstm_rec<<<128, 512>>>(preb, (l == 4) ? out : bufA,
                               Whh + (size_t)l * G4 * H_D, ah, al);
    }
}

// round 11
// speedup vs baseline: 1.6849x; 1.0233x over previous
#include <cuda_runtime.h>
#include <cuda_bf16.h>
#include <mma.h>
#include <cstdint>

using namespace nvcuda;

#define T_SEQ 512
#define B_SZ  256
#define IN_D  64
#define H_D   128
#define G4    512
#define TB    (T_SEQ * B_SZ)

__device__ float g_bufA[TB * H_D];                  // f32 sink (layers 0-3)
__device__ float g_pre [TB * G4];                   // gate pre-activations
__device__ __nv_bfloat16 g_ah[TB * H_D];            // activations hi (bf16)
__device__ __nv_bfloat16 g_al[TB * H_D];            // activations lo (bf16)
__device__ __nv_bfloat16 g_wh[H_D * G4];            // W^T hi  [K][512]
__device__ __nv_bfloat16 g_wl[H_D * G4];            // W^T lo  [K][512]

// ---------------- helpers ----------------
__device__ __forceinline__ void fma2(unsigned long long &acc,
                                     unsigned long long a, unsigned long long b) {
    asm("fma.rn.f32x2 %0, %1, %2, %3;" : "=l"(acc) : "l"(a), "l"(b), "l"(acc));
}
__device__ __forceinline__ unsigned long long pack2(float lo, float hi) {
    unsigned long long r;
    asm("mov.b64 %0, {%1, %2};" : "=l"(r) : "f"(lo), "f"(hi));
    return r;
}
__device__ __forceinline__ float sum2(unsigned long long v) {
    float lo, hi;
    asm("mov.b64 {%0, %1}, %2;" : "=f"(lo), "=f"(hi) : "l"(v));
    return lo + hi;
}
__device__ __forceinline__ float fsig(float x) {
    return __fdividef(1.0f, 1.0f + __expf(-x));
}
__device__ __forceinline__ float ftanh(float x) {
    return __fdividef(2.0f, 1.0f + __expf(-2.0f * x)) - 1.0f;
}
__device__ __forceinline__ void split2(float a, float b,
                                       __nv_bfloat162 &h, __nv_bfloat162 &l) {
    const __nv_bfloat16 ha = __float2bfloat16_rn(a);
    const __nv_bfloat16 hb = __float2bfloat16_rn(b);
    h.x = ha; h.y = hb;
    l.x = __float2bfloat16_rn(a - __bfloat162float(ha));
    l.y = __float2bfloat16_rn(b - __bfloat162float(hb));
}

// ============================================================================
// xconvert: f32 -> bf16 hi/lo (layer-0 input only)
// ============================================================================
__global__ void xconvert(const float* __restrict__ x,
                         __nv_bfloat16* __restrict__ xh,
                         __nv_bfloat16* __restrict__ xl, int n4) {
    const int i = blockIdx.x * blockDim.x + threadIdx.x;
    if (i >= n4) return;
    const float4 v = ((const float4*)x)[i];
    __nv_bfloat162 h0, l0, h1, l1;
    split2(v.x, v.y, h0, l0);
    split2(v.z, v.w, h1, l1);
    ((__nv_bfloat162*)xh)[2 * i]     = h0;
    ((__nv_bfloat162*)xh)[2 * i + 1] = h1;
    ((__nv_bfloat162*)xl)[2 * i]     = l0;
    ((__nv_bfloat162*)xl)[2 * i + 1] = l1;
}

// ============================================================================
// wconvert: W[512][K] f32 -> W^T hi/lo bf16 [K][512]
// ============================================================================
__global__ void wconvert(const float* __restrict__ W,
                         __nv_bfloat16* __restrict__ wh,
                         __nv_bfloat16* __restrict__ wl, int K) {
    const int e = blockIdx.x * blockDim.x + threadIdx.x;
    if (e >= K * G4) return;
    const int k = e >> 9, n = e & 511;
    const float v = W[(size_t)n * K + k];
    const __nv_bfloat16 h = __float2bfloat16_rn(v);
    wh[e] = h;
    wl[e] = __float2bfloat16_rn(v - __bfloat162float(h));
}

// ============================================================================
// pregemm (R10-measured-good): pre = A @ W^T + bias, pre-split bf16 operands
// ============================================================================
template<int K>
__global__ void __launch_bounds__(256, 2)
pregemm(const __nv_bfloat16* __restrict__ Ahg,   // [TB][K]
        const __nv_bfloat16* __restrict__ Alg,
        const __nv_bfloat16* __restrict__ Bhg,   // [K][512]
        const __nv_bfloat16* __restrict__ Blg,
        const float* __restrict__ bih, const float* __restrict__ bhh,
        float* __restrict__ pre)
{
    constexpr int AS = K + 8;
    constexpr int BS = 128 + 8;
    extern __shared__ __align__(256) char smp[];
    float* bias = (float*)smp;
    __nv_bfloat16* Ah = (__nv_bfloat16*)(smp + 512);   // [64][AS]
    __nv_bfloat16* Al = Ah + 64 * AS;
    __nv_bfloat16* Bh = Al + 64 * AS;                  // [K][BS]
    __nv_bfloat16* Bl = Bh + K * BS;
    float* Dsm = (float*)(smp + 512);                  // [64][128] reuse

    const int tid = threadIdx.x;
    const int wid = tid >> 5;
    const int m0 = (int)(blockIdx.x >> 2) * 64;
    const int n0 = (int)(blockIdx.x & 3) * 128;

    if (tid < 128) bias[tid] = bih[n0 + tid] + bhh[n0 + tid];

    for (int i = tid; i < 64 * K / 8; i += 256) {
        const int r = i / (K / 8), c8 = (i % (K / 8)) * 8;
        *(uint4*)(Ah + r * AS + c8) =
            *(const uint4*)(Ahg + (size_t)(m0 + r) * K + c8);
        *(uint4*)(Al + r * AS + c8) =
            *(const uint4*)(Alg + (size_t)(m0 + r) * K + c8);
    }
    for (int i = tid; i < K * 16; i += 256) {
        const int k = i >> 4, c8 = (i & 15) * 8;
        *(uint4*)(Bh + k * BS + c8) =
            *(const uint4*)(Bhg + (size_t)k * G4 + n0 + c8);
        *(uint4*)(Bl + k * BS + c8) =
            *(const uint4*)(Blg + (size_t)k * G4 + n0 + c8);
    }
    __syncthreads();

    const int wm = wid >> 1;
    const int wn = wid & 1;

    wmma::fragment<wmma::accumulator, 16, 16, 16, float> acc[4];
#pragma unroll
    for (int ni = 0; ni < 4; ni++) wmma::fill_fragment(acc[ni], 0.0f);

#pragma unroll
    for (int ks = 0; ks < K / 16; ks++) {
        wmma::fragment<wmma::matrix_a, 16, 16, 16, __nv_bfloat16,
                       wmma::row_major> ah, al;
        wmma::load_matrix_sync(ah, Ah + (wm * 16) * AS + ks * 16, AS);
        wmma::load_matrix_sync(al, Al + (wm * 16) * AS + ks * 16, AS);
#pragma unroll
        for (int ni = 0; ni < 4; ni++) {
            wmma::fragment<wmma::matrix_b, 16, 16, 16, __nv_bfloat16,
                           wmma::row_major> bhf, blf;
            wmma::load_matrix_sync(bhf,
                Bh + ks * 16 * BS + wn * 64 + ni * 16, BS);
            wmma::load_matrix_sync(blf,
                Bl + ks * 16 * BS + wn * 64 + ni * 16, BS);
            wmma::mma_sync(acc[ni], ah, bhf, acc[ni]);
            wmma::mma_sync(acc[ni], ah, blf, acc[ni]);
            wmma::mma_sync(acc[ni], al, bhf, acc[ni]);
        }
    }
    __syncthreads();

#pragma unroll
    for (int ni = 0; ni < 4; ni++)
        wmma::store_matrix_sync(
            Dsm + (wm * 16) * 128 + wn * 64 + ni * 16,
            acc[ni], 128, wmma::mem_row_major);
    __syncthreads();

    for (int i = tid; i < 64 * 32; i += 256) {
        const int r = i >> 5, c4 = (i & 31) * 4;
        float4 v = *(const float4*)(Dsm + r * 128 + c4);
        v.x += bias[c4];     v.y += bias[c4 + 1];
        v.z += bias[c4 + 2]; v.w += bias[c4 + 3];
        *(float4*)(pre + (size_t)(m0 + r) * G4 + n0 + c4) = v;
    }
}

// ============================================================================
// lstm_rec v2: 256 CTAs x 256 threads (2 CTAs/SM), cluster of 4.
// Cluster owns 4 batch rows; CTA rank owns h cols [32r,32r+32) of 4 gates.
// Thread = j (lane) x 4 gates x 16-k slice (warp w -> slice (w+2*rank)&7).
// Each LDS.128 of h feeds 8 fma2 (4 gates x 2). Co-resident CTAs are from
// clusters ~37 apart -> their barriers/epilogues overlap each other's dots.
// ============================================================================
__global__ void __launch_bounds__(256, 2) __cluster_dims__(4, 1, 1)
lstm_rec(const float* __restrict__ pre,   // [T,B,512], biases included
         float* __restrict__ out,         // [T,B,128] f32
         const float* __restrict__ Whh,   // [512,128]
         __nv_bfloat16* __restrict__ gh,  // [T,B,128] h hi
         __nv_bfloat16* __restrict__ gl)  // [T,B,128] h lo
{
    __shared__ float gbuf[8][4][128];                // [slice][b][4g*32j]
    __shared__ __align__(16) float hs[2][4][128];

    const int tid = threadIdx.x, lane = tid & 31, w = tid >> 5;
    uint32_t rank;
    asm("mov.u32 %0, %%cluster_ctarank;" : "=r"(rank));
    const int sl = (w + 2 * (int)rank) & 7;          // k-slice of this warp
    const int k0 = sl * 16;
    const bool own = (w < 2);                        // slices 2r, 2r+1
    const int b0 = (blockIdx.x >> 2) * 4;            // 4 batch rows / cluster

    // weights: 4 gate rows (one per gate, same j=lane) x 16 k, f32x2-packed
    unsigned long long Wr[4][8];
#pragma unroll
    for (int g = 0; g < 4; g++) {
        const int grow = g * H_D + (int)rank * 32 + lane;
#pragma unroll
        for (int i = 0; i < 8; i++)
            Wr[g][i] = pack2(Whh[grow * H_D + k0 + 2 * i],
                             Whh[grow * H_D + k0 + 2 * i + 1]);
    }

    // epilogue identity (tid < 128): cell (ob, oj)
    const int ob = tid >> 5, oj = tid & 31;          // ob 0..3 valid tid<128
    const int jglob = (int)rank * 32 + oj;
    float c_state = 0.0f;
    const float* pre_p = pre + ((size_t)b0 + ob) * G4 + jglob;
    float* out_p = out + ((size_t)b0 + ob) * H_D + jglob;
    __nv_bfloat16* gh_p = gh + ((size_t)b0 + ob) * H_D + jglob;
    __nv_bfloat16* gl_p = gl + ((size_t)b0 + ob) * H_D + jglob;

    for (int i = tid; i < 4 * H_D; i += 256) hs[0][i >> 7][i & 127] = 0.0f;
    __syncthreads();
    asm volatile("barrier.cluster.arrive.aligned;" ::: "memory");

    for (int t = 0; t < T_SEQ; t++) {
        const int cur = t & 1, nxt = cur ^ 1;

        float p0, p1, p2, p3;
        if (tid < 128) {
            p0 = pre_p[0];   p1 = pre_p[128];
            p2 = pre_p[256]; p3 = pre_p[384];
            pre_p += (size_t)B_SZ * G4;
        }

        unsigned long long acc[4][4];                // [g][b]
#pragma unroll
        for (int g = 0; g < 4; g++)
#pragma unroll
            for (int b = 0; b < 4; b++) acc[g][b] = 0ull;

        if (own) {   // local h columns (ordered by trailing __syncthreads)
#pragma unroll
            for (int kk = 0; kk < 4; kk++) {
                ulonglong2 v[4];
#pragma unroll
                for (int b = 0; b < 4; b++)
                    v[b] = *(const ulonglong2*)(&hs[cur][b][k0 + 4 * kk]);
#pragma unroll
                for (int g = 0; g < 4; g++)
#pragma unroll
                    for (int b = 0; b < 4; b++) {
                        fma2(acc[g][b], v[b].x, Wr[g][2 * kk]);
                        fma2(acc[g][b], v[b].y, Wr[g][2 * kk + 1]);
                    }
            }
#pragma unroll
            for (int g = 0; g < 4; g++)
#pragma unroll
                for (int b = 0; b < 4; b++)
                    gbuf[sl][b][g * 32 + lane] = sum2(acc[g][b]);
        }

        asm volatile("barrier.cluster.wait.aligned;" ::: "memory");

        if (!own) {  // peer h columns (published via DSMEM before the barrier)
#pragma unroll
            for (int kk = 0; kk < 4; kk++) {
                ulonglong2 v[4];
#pragma unroll
                for (int b = 0; b < 4; b++)
                    v[b] = *(const ulonglong2*)(&hs[cur][b][k0 + 4 * kk]);
#pragma unroll
                for (int g = 0; g < 4; g++)
#pragma unroll
                    for (int b = 0; b < 4; b++) {
                        fma2(acc[g][b], v[b].x, Wr[g][2 * kk]);
                        fma2(acc[g][b], v[b].y, Wr[g][2 * kk + 1]);
                    }
            }
#pragma unroll
            for (int g = 0; g < 4; g++)
#pragma unroll
                for (int b = 0; b < 4; b++)
                    gbuf[sl][b][g * 32 + lane] = sum2(acc[g][b]);
        }

        __syncthreads();

        if (tid < 128) {
            float gv0 = p0, gv1 = p1, gv2 = p2, gv3 = p3;
#pragma unroll
            for (int q = 0; q < 8; q++) {
                gv0 += gbuf[q][ob][oj];
                gv1 += gbuf[q][ob][32 + oj];
                gv2 += gbuf[q][ob][64 + oj];
                gv3 += gbuf[q][ob][96 + oj];
            }
            const float ig = fsig(gv0), fg = fsig(gv1);
            const float gg = ftanh(gv2), og = fsig(gv3);
            c_state = fg * c_state + ig * gg;
            const float h = og * ftanh(c_state);

            if (t + 1 < T_SEQ) {
                float* hp = &hs[nxt][ob][jglob];
                *hp = h;
                const uint32_t la = (uint32_t)__cvta_generic_to_shared(hp);
#pragma unroll
                for (int pr = 0; pr < 4; pr++)
                    if (pr != (int)rank)
                        asm volatile("{ .reg .b32 ra;\n\t"
                            "mapa.shared::cluster.u32 ra, %0, %1;\n\t"
                            "st.shared::cluster.f32 [ra], %2; }"
                            :: "r"(la), "r"(pr), "f"(h) : "memory");
            }
            *out_p = h;
            out_p += (size_t)B_SZ * H_D;
            const __nv_bfloat16 hh = __float2bfloat16_rn(h);
            *gh_p = hh;
            *gl_p = __float2bfloat16_rn(h - __bfloat162float(hh));
            gh_p += (size_t)B_SZ * H_D;
            gl_p += (size_t)B_SZ * H_D;
        }

        if (t + 1 < T_SEQ)
            asm volatile("barrier.cluster.arrive.aligned;" ::: "memory");
        __syncthreads();
    }
}

// ============================================================================
extern "C" void kernel_launch(void* const* d_in, const int* in_sizes, int n_in,
                              void* d_out, int out_size) {
    const float* x     = (const float*)d_in[0];
    const float* Wih0  = (const float*)d_in[1];
    const float* Wrest = (const float*)d_in[2];
    const float* Whh   = (const float*)d_in[3];
    const float* bih   = (const float*)d_in[4];
    const float* bhh   = (const float*)d_in[5];
    float* out = (float*)d_out;

    float *bufA, *preb;
    __nv_bfloat16 *ah, *al, *wh, *wl;
    cudaGetSymbolAddress((void**)&bufA, g_bufA);
    cudaGetSymbolAddress((void**)&preb, g_pre);
    cudaGetSymbolAddress((void**)&ah, g_ah);
    cudaGetSymbolAddress((void**)&al, g_al);
    cudaGetSymbolAddress((void**)&wh, g_wh);
    cudaGetSymbolAddress((void**)&wl, g_wl);

    const int SP64  = 512 + 64 * 72  * 2 * 2 + 64  * 136 * 2 * 2;  //  53760
    const int SP128 = 512 + 64 * 136 * 2 * 2 + 128 * 136 * 2 * 2;  // 104960
    cudaFuncSetAttribute(pregemm<64>,
        cudaFuncAttributeMaxDynamicSharedMemorySize, SP64);
    cudaFuncSetAttribute(pregemm<128>,
        cudaFuncAttributeMaxDynamicSharedMemorySize, SP128);

    // layer 0
    xconvert<<<TB * IN_D / 4 / 256, 256>>>(x, ah, al, TB * IN_D / 4);
    wconvert<<<64 * G4 / 256, 256>>>(Wih0, wh, wl, 64);
    pregemm<64><<<8192, 256, SP64>>>(ah, al, wh, wl, bih, bhh, preb);
    lstm_rec<<<256, 256>>>(preb, bufA, Whh, ah, al);

    // layers 1..4
    for (int l = 1; l < 5; l++) {
        wconvert<<<128 * G4 / 256, 256>>>(
            Wrest + (size_t)(l - 1) * G4 * H_D, wh, wl, 128);
        pregemm<128><<<8192, 256, SP128>>>(
            ah, al, wh, wl, bih + (size_t)l * G4, bhh + (size_t)l * G4, preb);
        lstm_rec<<<256, 256>>>(preb, (l == 4) ? out : bufA,
                               Whh + (size_t)l * G4 * H_D, ah, al);
    }
}